// round 1
// baseline (speedup 1.0000x reference)
#include <cuda_runtime.h>
#include <cuda_bf16.h>

#define BB 4
#define KK 128
#define GG 128

// Output layout (flattened tuple, float32):
// rois [B,K,4] | obj [B,K,1024] | deltas [B,K,4] | ranks [B,K] | spatial [B,K,32,32]
#define OFF_ROIS    0
#define OFF_OBJ     (BB*KK*4)                 // 2048
#define OFF_DELTAS  (OFF_OBJ + BB*KK*1024)    // 526336
#define OFF_RANKS   (OFF_DELTAS + BB*KK*4)    // 528384
#define OFF_SPATIAL (OFF_RANKS + BB*KK)       // 528896

__device__ int   g_perm[BB*KK];
__device__ float g_roigt[BB*KK*4];

// One block per image, one thread per proposal.
__global__ void __launch_bounds__(KK) k1_assign(
    const float* __restrict__ props, const float* __restrict__ gtb,
    const int* __restrict__ gtr, float* __restrict__ out)
{
    int b = blockIdx.x;
    int k = threadIdx.x;

    __shared__ float sg[GG*4];
    __shared__ unsigned pm[4];

    const float* gbase = gtb + b*GG*4;
    for (int i = k; i < GG*4; i += KK) sg[i] = gbase[i];
    __syncthreads();

    float4 p = ((const float4*)(props + b*KK*4))[k];   // (y1,x1,y2,x2)
    float ap = (p.z - p.x) * (p.w - p.y);

    float best = -1.0f;
    int assign = 0;
    #pragma unroll 4
    for (int g = 0; g < GG; g++) {
        float gy1 = sg[g*4+0], gx1 = sg[g*4+1], gy2 = sg[g*4+2], gx2 = sg[g*4+3];
        float iy1 = fmaxf(p.x, gy1), ix1 = fmaxf(p.y, gx1);
        float iy2 = fminf(p.z, gy2), ix2 = fminf(p.w, gx2);
        float inter = fmaxf(ix2 - ix1, 0.0f) * fmaxf(iy2 - iy1, 0.0f);
        float ag = (gy2 - gy1) * (gx2 - gx1);
        float iou = inter / (ap + ag - inter);
        if (iou > best) { best = iou; assign = g; }   // first-max tie-break == jnp.argmax
    }
    bool pos = (best >= 0.5f);

    // Stable partition: positives first (original order), then negatives.
    int warp = k >> 5, lane = k & 31;
    unsigned wm = __ballot_sync(0xffffffffu, pos);
    if (lane == 0) pm[warp] = wm;
    __syncthreads();
    int npos = 0, before = 0;
    #pragma unroll
    for (int w = 0; w < 4; w++) {
        int c = __popc(pm[w]);
        npos += c;
        if (w < warp) before += c;
    }
    before += __popc(pm[warp] & ((1u << lane) - 1u));
    int dest = pos ? before : (npos + (k - before));

    // rois
    ((float4*)(out + OFF_ROIS + b*KK*4))[dest] = p;

    float4 d  = make_float4(0.f, 0.f, 0.f, 0.f);
    float4 rg = make_float4(0.f, 0.f, 0.f, 0.f);
    int rk = 0;
    if (pos) {
        float gy1 = sg[assign*4+0], gx1 = sg[assign*4+1];
        float gy2 = sg[assign*4+2], gx2 = sg[assign*4+3];
        float h  = p.z - p.x,  w  = p.w - p.y;
        float cy = p.x + 0.5f*h, cx = p.y + 0.5f*w;
        float gh = gy2 - gy1,  gw = gx2 - gx1;
        float gcy = gy1 + 0.5f*gh, gcx = gx1 + 0.5f*gw;
        d.x = ((gcy - cy) / h) / 0.1f;
        d.y = ((gcx - cx) / w) / 0.1f;
        d.z = logf(gh / h) / 0.2f;
        d.w = logf(gw / w) / 0.2f;
        rg = make_float4(gy1, gx1, gy2, gx2);
        rk = gtr[b*GG + assign];
    }
    ((float4*)(out + OFF_DELTAS + b*KK*4))[dest] = d;
    out[OFF_RANKS + b*KK + dest] = (float)rk;
    g_perm[b*KK + dest] = k;
    ((float4*)g_roigt)[b*KK + dest] = rg;
}

// One block per (image, output-slot): gather obj row + closed-form spatial feat.
// resize_with_pad at ratio 20 => out[i,j] = 0.25 * ry(i) * cx(j), where
// ry counts r in {20i+9, 20i+10} strictly inside (y1,y2), cx likewise for x.
__global__ void __launch_bounds__(256) k2_gather_spatial(
    const float* __restrict__ feat, float* __restrict__ out)
{
    int bk = blockIdx.x;          // b*K + dest slot
    int b  = bk >> 7;
    int t  = threadIdx.x;

    // obj gather: 1024 floats = 256 float4, one per thread
    int src = g_perm[bk];
    const float4* in = (const float4*)(feat + (size_t)(b*KK + src)*1024);
    float4* op = (float4*)(out + OFF_OBJ + (size_t)bk*1024);
    op[t] = in[t];

    // spatial feature from roi_gt box
    float4 rg = ((const float4*)g_roigt)[bk];

    const float wy1 = 128.0f/1023.0f;
    const float wsy = (895.0f/1023.0f) - (128.0f/1023.0f);
    // x-window: shift 0, scale 1
    float by1 = (rg.x - wy1) / wsy;
    float by2 = (rg.z - wy1) / wsy;
    int py1 = (int)rintf(__fmul_rn(by1, 479.0f));
    int px1 = (int)rintf(__fmul_rn(rg.y, 639.0f));
    int py2 = (int)rintf(__fadd_rn(__fmul_rn(by2, 479.0f), 1.0f));
    int px2 = (int)rintf(__fadd_rn(__fmul_rn(rg.w, 639.0f), 1.0f));
    int area = (py2 - py1) * (px2 - px1);
    if (area <= 0) { py1 = px1 = py2 = px2 = 0; }

    float* sp = out + OFF_SPATIAL + (size_t)bk*1024;
    #pragma unroll
    for (int e = t; e < 1024; e += 256) {
        int row = e >> 5, col = e & 31;
        float v = 0.0f;
        if (row >= 4 && row < 28) {
            int i  = row - 4;
            int r0 = 20*i + 9,   r1 = r0 + 1;
            int c0 = 20*col + 9, c1 = c0 + 1;
            int ry = (int)((py1 < r0) && (r0 < py2)) + (int)((py1 < r1) && (r1 < py2));
            int cx = (int)((px1 < c0) && (c0 < px2)) + (int)((px1 < c1) && (c1 < px2));
            v = 0.25f * (float)(ry * cx);
        }
        sp[e] = v;
    }
}

extern "C" void kernel_launch(void* const* d_in, const int* in_sizes, int n_in,
                              void* d_out, int out_size)
{
    const float* props = (const float*)d_in[0];   // [4,128,4]
    const float* feat  = (const float*)d_in[1];   // [4,128,1,1,1024]
    const float* gtb   = (const float*)d_in[2];   // [4,128,4]
    const int*   gtr   = (const int*)d_in[3];     // [4,128]
    float* out = (float*)d_out;

    k1_assign<<<BB, KK>>>(props, gtb, gtr, out);
    k2_gather_spatial<<<BB*KK, 256>>>(feat, out);
}

// round 2
// speedup vs baseline: 1.0691x; 1.0691x over previous
#include <cuda_runtime.h>
#include <cuda_bf16.h>

#define BB 4
#define KK 128
#define GG 128

// Output layout (flattened tuple, float32):
// rois [B,K,4] | obj [B,K,1024] | deltas [B,K,4] | ranks [B,K] | spatial [B,K,32,32]
#define OFF_ROIS    0
#define OFF_OBJ     (BB*KK*4)                 // 2048
#define OFF_DELTAS  (OFF_OBJ + BB*KK*1024)    // 526336
#define OFF_RANKS   (OFF_DELTAS + BB*KK*4)    // 528384
#define OFF_SPATIAL (OFF_RANKS + BB*KK)       // 528896

__device__ int    g_perm[BB*KK];
__device__ float4 g_roigt[BB*KK];
__device__ int    g_flag[BB];   // zero at module load; stays 1 across replays (values identical -> benign)

__global__ void __launch_bounds__(256) fused_kernel(
    const float* __restrict__ props, const float* __restrict__ feat,
    const float* __restrict__ gtb,   const int* __restrict__ gtr,
    float* __restrict__ out)
{
    const int bk = blockIdx.x;      // global slot index: b*128 + dest
    const int t  = threadIdx.x;

    __shared__ float4 sgt[GG];      // gt boxes
    __shared__ float4 spr[KK];      // proposals
    __shared__ int    sassign[KK];
    __shared__ unsigned char sposf[KK];
    __shared__ unsigned pm[4];

    // ───────────────────────── producer: blocks 0..3 (one per image) ─────────────────────────
    if (bk < BB) {
        const int b = bk;
        if (t < GG)      sgt[t]       = ((const float4*)gtb)[b*GG + t];
        else             spr[t - GG]  = ((const float4*)props)[b*KK + (t - GG)];
        __syncthreads();

        // 2 threads per proposal: even lane scans g in [0,64), odd lane [64,128)
        const int p    = t >> 1;
        const int half = t & 1;
        float4 pp = spr[p];
        const float ap = (pp.z - pp.x) * (pp.w - pp.y);

        float best = -1.0f;
        int assign = half * 64;
        const int g0 = half * 64;
        #pragma unroll 4
        for (int g = g0; g < g0 + 64; g++) {
            float4 gg = sgt[g];
            float iy1 = fmaxf(pp.x, gg.x), ix1 = fmaxf(pp.y, gg.y);
            float iy2 = fminf(pp.z, gg.z), ix2 = fminf(pp.w, gg.w);
            float inter = fmaxf(ix2 - ix1, 0.0f) * fmaxf(iy2 - iy1, 0.0f);
            float ag = (gg.z - gg.x) * (gg.w - gg.y);
            float iou = inter / (ap + ag - inter);
            if (iou > best) { best = iou; assign = g; }  // strict > == first-max within half
        }
        // combine halves; low half wins ties -> first-max overall (jnp.argmax semantics)
        float ob = __shfl_down_sync(0xffffffffu, best, 1);
        int   oa = __shfl_down_sync(0xffffffffu, assign, 1);
        if (half == 0) {
            if (ob > best) { best = ob; assign = oa; }
            sposf[p]   = (best >= 0.5f) ? 1 : 0;
            sassign[p] = assign;
        }
        __syncthreads();

        // stable partition: positives first, original order preserved
        bool pos = false;
        if (t < KK) {
            pos = (sposf[t] != 0);
            unsigned wm = __ballot_sync(0xffffffffu, pos);
            if ((t & 31) == 0) pm[t >> 5] = wm;
        }
        __syncthreads();
        if (t < KK) {
            const int k = t;
            int warp = k >> 5, lane = k & 31;
            int npos = 0, before = 0;
            #pragma unroll
            for (int w = 0; w < 4; w++) {
                int c = __popc(pm[w]);
                npos += c;
                if (w < warp) before += c;
            }
            before += __popc(pm[warp] & ((1u << lane) - 1u));
            int dest = pos ? before : (npos + (k - before));

            float4 pk = spr[k];
            ((float4*)(out + OFF_ROIS + b*KK*4))[dest] = pk;

            float4 d  = make_float4(0.f, 0.f, 0.f, 0.f);
            float4 rg = make_float4(0.f, 0.f, 0.f, 0.f);
            int rk = 0;
            if (pos) {
                int a = sassign[k];
                float4 gg = sgt[a];
                float h  = pk.z - pk.x,  w  = pk.w - pk.y;
                float cy = pk.x + 0.5f*h, cx = pk.y + 0.5f*w;
                float gh = gg.z - gg.x,  gw = gg.w - gg.y;
                float gcy = gg.x + 0.5f*gh, gcx = gg.y + 0.5f*gw;
                d.x = ((gcy - cy) / h) / 0.1f;
                d.y = ((gcx - cx) / w) / 0.1f;
                d.z = logf(gh / h) / 0.2f;
                d.w = logf(gw / w) / 0.2f;
                rg = gg;
                rk = gtr[b*GG + a];
            }
            ((float4*)(out + OFF_DELTAS + b*KK*4))[dest] = d;
            out[OFF_RANKS + b*KK + dest] = (float)rk;
            g_perm[b*KK + dest]  = k;
            g_roigt[b*KK + dest] = rg;
        }
        __threadfence();
        __syncthreads();
        if (t == 0) atomicExch(&g_flag[b], 1);   // release
    }

    // ───────────────────────── consumer: every block handles slot bk ─────────────────────────
    const int b = bk >> 7;
    if (t == 0) {
        volatile int* f = (volatile int*)&g_flag[b];
        while (*f == 0) { __nanosleep(64); }
        __threadfence();   // acquire
    }
    __syncthreads();

    // obj gather: 1024 floats = 256 float4, one per thread
    int src = g_perm[bk];
    const float4* in = (const float4*)(feat + (size_t)(b*KK + src) * 1024);
    float4* op = (float4*)(out + OFF_OBJ + (size_t)bk * 1024);
    op[t] = in[t];

    // spatial feature from roi_gt box (closed-form resize_with_pad at ratio 20)
    float4 rg = g_roigt[bk];
    const float wy1 = 128.0f/1023.0f;
    const float wsy = (895.0f/1023.0f) - (128.0f/1023.0f);
    float by1 = (rg.x - wy1) / wsy;
    float by2 = (rg.z - wy1) / wsy;
    int py1 = (int)rintf(__fmul_rn(by1, 479.0f));
    int px1 = (int)rintf(__fmul_rn(rg.y, 639.0f));
    int py2 = (int)rintf(__fadd_rn(__fmul_rn(by2, 479.0f), 1.0f));
    int px2 = (int)rintf(__fadd_rn(__fmul_rn(rg.w, 639.0f), 1.0f));
    int area = (py2 - py1) * (px2 - px1);
    if (area <= 0) { py1 = px1 = py2 = px2 = 0; }

    // one float4 (4 consecutive cols, same row) per thread: e = 4t
    int row  = t >> 3;
    int col0 = (t & 7) << 2;
    float4 v = make_float4(0.f, 0.f, 0.f, 0.f);
    if (row >= 4 && row < 28) {
        int i  = row - 4;
        int r0 = 20*i + 9, r1 = r0 + 1;
        int ry = (int)((py1 < r0) && (r0 < py2)) + (int)((py1 < r1) && (r1 < py2));
        if (ry) {
            float fr = 0.25f * (float)ry;
            #pragma unroll
            for (int c = 0; c < 4; c++) {
                int col = col0 + c;
                int c0 = 20*col + 9, c1 = c0 + 1;
                int cx = (int)((px1 < c0) && (c0 < px2)) + (int)((px1 < c1) && (c1 < px2));
                ((float*)&v)[c] = fr * (float)cx;
            }
        }
    }
    ((float4*)(out + OFF_SPATIAL + (size_t)bk * 1024))[t] = v;
}

extern "C" void kernel_launch(void* const* d_in, const int* in_sizes, int n_in,
                              void* d_out, int out_size)
{
    const float* props = (const float*)d_in[0];   // [4,128,4]
    const float* feat  = (const float*)d_in[1];   // [4,128,1,1,1024]
    const float* gtb   = (const float*)d_in[2];   // [4,128,4]
    const int*   gtr   = (const int*)d_in[3];     // [4,128]
    float* out = (float*)d_out;

    fused_kernel<<<BB*KK, 256>>>(props, feat, gtb, gtr, out);
}

// round 9
// speedup vs baseline: 1.0821x; 1.0122x over previous
#include <cuda_runtime.h>
#include <cuda_bf16.h>

#define BB 4
#define KK 128
#define GG 128

// Output layout (flattened tuple, float32):
// rois [B,K,4] | obj [B,K,1024] | deltas [B,K,4] | ranks [B,K] | spatial [B,K,32,32]
#define OFF_ROIS    0
#define OFF_OBJ     (BB*KK*4)                 // 2048
#define OFF_DELTAS  (OFF_OBJ + BB*KK*1024)    // 526336
#define OFF_RANKS   (OFF_DELTAS + BB*KK*4)    // 528384
#define OFF_SPATIAL (OFF_RANKS + BB*KK)       // 528896

// One fully independent block per output slot. Each block redundantly
// recomputes its image's assignment (cheap) -> zero inter-block sync.
__global__ void __launch_bounds__(256) fused_kernel(
    const float* __restrict__ props, const float* __restrict__ feat,
    const float* __restrict__ gtb,   const int* __restrict__ gtr,
    float* __restrict__ out)
{
    const int bk   = blockIdx.x;        // b*128 + slot
    const int b    = bk >> 7;
    const int slot = bk & 127;
    const int t    = threadIdx.x;

    __shared__ float4 sgt[GG];
    __shared__ float4 spr[KK];
    __shared__ int    sassign[KK];
    __shared__ unsigned char sposf[KK];
    __shared__ unsigned pm[4];
    __shared__ short  sperm[KK];

    // load gt boxes + proposals for this image (one float4 per thread)
    if (t < GG) sgt[t]      = ((const float4*)gtb)[b*GG + t];
    else        spr[t-GG]   = ((const float4*)props)[b*KK + (t - GG)];
    __syncthreads();

    // ── assignment: 2 threads per proposal, 64 GTs each ──
    {
        const int p    = t >> 1;
        const int half = t & 1;
        float4 pp = spr[p];
        const float ap = (pp.z - pp.x) * (pp.w - pp.y);

        float best = -1.0f;
        int assign = half * 64;
        const int g0 = half * 64;
        #pragma unroll 8
        for (int g = g0; g < g0 + 64; g++) {
            float4 gg = sgt[g];
            float iy1 = fmaxf(pp.x, gg.x), ix1 = fmaxf(pp.y, gg.y);
            float iy2 = fminf(pp.z, gg.z), ix2 = fminf(pp.w, gg.w);
            float inter = fmaxf(ix2 - ix1, 0.0f) * fmaxf(iy2 - iy1, 0.0f);
            float ag = (gg.z - gg.x) * (gg.w - gg.y);
            float iou = inter / (ap + ag - inter);
            if (iou > best) { best = iou; assign = g; }  // strict > == first-max within half
        }
        // combine halves; low half wins ties -> first-max overall (jnp.argmax semantics)
        float ob = __shfl_down_sync(0xffffffffu, best, 1);
        int   oa = __shfl_down_sync(0xffffffffu, assign, 1);
        if (half == 0) {
            if (ob > best) { best = ob; assign = oa; }
            sposf[p]   = (best >= 0.5f) ? 1 : 0;
            sassign[p] = assign;
        }
    }
    __syncthreads();

    // ── stable partition (warps 0-3 handle proposals 0..127) ──
    if (t < KK) {
        bool pos = (sposf[t] != 0);
        unsigned wm = __ballot_sync(0xffffffffu, pos);
        if ((t & 31) == 0) pm[t >> 5] = wm;
    }
    __syncthreads();
    if (t < KK) {
        const int k = t;
        int warp = k >> 5, lane = k & 31;
        bool pos = (sposf[k] != 0);
        int npos = 0, before = 0;
        #pragma unroll
        for (int w = 0; w < 4; w++) {
            int c = __popc(pm[w]);
            npos += c;
            if (w < warp) before += c;
        }
        before += __popc(pm[warp] & ((1u << lane) - 1u));
        int dest = pos ? before : (npos + (k - before));
        sperm[dest] = (short)k;
    }
    __syncthreads();

    // ── this block's slot ──
    const int  src = sperm[slot];
    const bool pos = (sposf[src] != 0);
    const int  a   = sassign[src];

    float4 rg = pos ? sgt[a] : make_float4(0.f, 0.f, 0.f, 0.f);

    if (t == 0) {
        float4 pk = spr[src];
        ((float4*)(out + OFF_ROIS + b*KK*4))[slot] = pk;
        float4 d = make_float4(0.f, 0.f, 0.f, 0.f);
        int rk = 0;
        if (pos) {
            float4 gg = rg;
            float h  = pk.z - pk.x,  w  = pk.w - pk.y;
            float cy = pk.x + 0.5f*h, cx = pk.y + 0.5f*w;
            float gh = gg.z - gg.x,  gw = gg.w - gg.y;
            float gcy = gg.x + 0.5f*gh, gcx = gg.y + 0.5f*gw;
            d.x = ((gcy - cy) / h) / 0.1f;
            d.y = ((gcx - cx) / w) / 0.1f;
            d.z = logf(gh / h) / 0.2f;
            d.w = logf(gw / w) / 0.2f;
            rk = gtr[b*GG + a];
        }
        ((float4*)(out + OFF_DELTAS + b*KK*4))[slot] = d;
        out[OFF_RANKS + b*KK + slot] = (float)rk;
    }

    // ── obj gather: 1024 floats = 256 float4, one per thread ──
    {
        const float4* in = (const float4*)(feat + (size_t)(b*KK + src) * 1024);
        float4* op = (float4*)(out + OFF_OBJ + (size_t)bk * 1024);
        op[t] = in[t];
    }

    // ── spatial feature (closed-form resize_with_pad, ratio 20) ──
    const float wy1 = 128.0f/1023.0f;
    const float wsy = (895.0f/1023.0f) - (128.0f/1023.0f);
    float by1 = (rg.x - wy1) / wsy;
    float by2 = (rg.z - wy1) / wsy;
    int py1 = (int)rintf(__fmul_rn(by1, 479.0f));
    int px1 = (int)rintf(__fmul_rn(rg.y, 639.0f));
    int py2 = (int)rintf(__fadd_rn(__fmul_rn(by2, 479.0f), 1.0f));
    int px2 = (int)rintf(__fadd_rn(__fmul_rn(rg.w, 639.0f), 1.0f));
    int area = (py2 - py1) * (px2 - px1);
    if (area <= 0) { py1 = px1 = py2 = px2 = 0; }

    int row  = t >> 3;          // 0..31
    int col0 = (t & 7) << 2;    // 0,4,...,28
    float4 v = make_float4(0.f, 0.f, 0.f, 0.f);
    if (row >= 4 && row < 28) {
        int i  = row - 4;
        int r0 = 20*i + 9, r1 = r0 + 1;
        int ry = (int)((py1 < r0) && (r0 < py2)) + (int)((py1 < r1) && (r1 < py2));
        if (ry) {
            float fr = 0.25f * (float)ry;
            #pragma unroll
            for (int c = 0; c < 4; c++) {
                int col = col0 + c;
                int c0 = 20*col + 9, c1 = c0 + 1;
                int cx = (int)((px1 < c0) && (c0 < px2)) + (int)((px1 < c1) && (c1 < px2));
                ((float*)&v)[c] = fr * (float)cx;
            }
        }
    }
    ((float4*)(out + OFF_SPATIAL + (size_t)bk * 1024))[t] = v;
}

extern "C" void kernel_launch(void* const* d_in, const int* in_sizes, int n_in,
                              void* d_out, int out_size)
{
    const float* props = (const float*)d_in[0];   // [4,128,4]
    const float* feat  = (const float*)d_in[1];   // [4,128,1,1,1024]
    const float* gtb   = (const float*)d_in[2];   // [4,128,4]
    const int*   gtr   = (const int*)d_in[3];     // [4,128]
    float* out = (float*)d_out;

    fused_kernel<<<BB*KK, 256>>>(props, feat, gtb, gtr, out);
}

// round 11
// speedup vs baseline: 2.9367x; 2.7139x over previous
#include <cuda_runtime.h>
#include <cuda_bf16.h>

#define BB 4
#define KK 128
#define GG 128
#define SPB 4                       // slots per block
#define NBLK (BB*KK/SPB)            // 128 blocks
#define BLKS_PER_IMG (KK/SPB)       // 32

// Output layout (flattened tuple, float32):
// rois [B,K,4] | obj [B,K,1024] | deltas [B,K,4] | ranks [B,K] | spatial [B,K,32,32]
#define OFF_ROIS    0
#define OFF_OBJ     (BB*KK*4)                 // 2048
#define OFF_DELTAS  (OFF_OBJ + BB*KK*1024)    // 526336
#define OFF_RANKS   (OFF_DELTAS + BB*KK*4)    // 528384
#define OFF_SPATIAL (OFF_RANKS + BB*KK)       // 528896

// Independent blocks; each redundantly computes its image's assignment with a
// DIVISION-FREE IoU argmax (cross-multiplied comparisons), then emits 4 slots.
__global__ void __launch_bounds__(256) fused_kernel(
    const float* __restrict__ props, const float* __restrict__ feat,
    const float* __restrict__ gtb,   const int* __restrict__ gtr,
    float* __restrict__ out)
{
    const int blk   = blockIdx.x;
    const int b     = blk / BLKS_PER_IMG;
    const int slot0 = (blk % BLKS_PER_IMG) * SPB;
    const int t     = threadIdx.x;

    __shared__ float4 sgt[GG];
    __shared__ float4 spr[KK];
    __shared__ float  sag[GG];
    __shared__ int    sassign[KK];
    __shared__ unsigned char sposf[KK];
    __shared__ unsigned pm[4];
    __shared__ short  sperm[KK];

    // load gt boxes + proposals (one float4 per thread)
    if (t < GG) sgt[t]     = ((const float4*)gtb)[b*GG + t];
    else        spr[t-GG]  = ((const float4*)props)[b*KK + (t - GG)];
    __syncthreads();
    if (t < GG) {
        float4 gg = sgt[t];
        sag[t] = (gg.z - gg.x) * (gg.w - gg.y);
    }
    __syncthreads();

    // ── assignment: 2 threads per proposal, 64 GTs each, division-free ──
    {
        const int p    = t >> 1;
        const int half = t & 1;
        float4 pp = spr[p];
        const float ap = (pp.z - pp.x) * (pp.w - pp.y);

        // best kept as (inter, union) pair; iou_a > iou_b <=> ia*ub > ib*ua (u>0)
        float bi = -1.0f, bu = 1.0f;
        int assign = half * 64;
        const int g0 = half * 64;
        #pragma unroll 8
        for (int g = g0; g < g0 + 64; g++) {
            float4 gg = sgt[g];
            float iy1 = fmaxf(pp.x, gg.x), ix1 = fmaxf(pp.y, gg.y);
            float iy2 = fminf(pp.z, gg.z), ix2 = fminf(pp.w, gg.w);
            float inter = fmaxf(ix2 - ix1, 0.0f) * fmaxf(iy2 - iy1, 0.0f);
            float u = ap + sag[g] - inter;
            if (inter * bu > bi * u) { bi = inter; bu = u; assign = g; }  // strict > == first-max
        }
        // combine halves; low half wins ties -> first-max overall
        float oi = __shfl_down_sync(0xffffffffu, bi, 1);
        float ou = __shfl_down_sync(0xffffffffu, bu, 1);
        int   oa = __shfl_down_sync(0xffffffffu, assign, 1);
        if (half == 0) {
            if (oi * bu > bi * ou) { bi = oi; bu = ou; assign = oa; }
            sposf[p]   = (2.0f * bi >= bu) ? 1 : 0;   // iou >= 0.5, division-free
            sassign[p] = assign;
        }
    }
    __syncthreads();

    // ── stable partition (positives first, original order) ──
    if (t < KK) {
        bool pos = (sposf[t] != 0);
        unsigned wm = __ballot_sync(0xffffffffu, pos);
        if ((t & 31) == 0) pm[t >> 5] = wm;
    }
    __syncthreads();
    if (t < KK) {
        const int k = t;
        int warp = k >> 5, lane = k & 31;
        bool pos = (sposf[k] != 0);
        int npos = 0, before = 0;
        #pragma unroll
        for (int w = 0; w < 4; w++) {
            int c = __popc(pm[w]);
            npos += c;
            if (w < warp) before += c;
        }
        before += __popc(pm[warp] & ((1u << lane) - 1u));
        int dest = pos ? before : (npos + (k - before));
        sperm[dest] = (short)k;
    }
    __syncthreads();

    // ── scalar outputs: threads 0..3 handle the block's 4 slots ──
    if (t < SPB) {
        const int slot = slot0 + t;
        const int src  = sperm[slot];
        const bool pos = (sposf[src] != 0);
        float4 pk = spr[src];
        ((float4*)(out + OFF_ROIS + b*KK*4))[slot] = pk;
        float4 d = make_float4(0.f, 0.f, 0.f, 0.f);
        int rk = 0;
        if (pos) {
            float4 gg = sgt[sassign[src]];
            float h  = pk.z - pk.x,  w  = pk.w - pk.y;
            float cy = pk.x + 0.5f*h, cx = pk.y + 0.5f*w;
            float gh = gg.z - gg.x,  gw = gg.w - gg.y;
            float gcy = gg.x + 0.5f*gh, gcx = gg.y + 0.5f*gw;
            d.x = ((gcy - cy) / h) / 0.1f;
            d.y = ((gcx - cx) / w) / 0.1f;
            d.z = logf(gh / h) / 0.2f;
            d.w = logf(gw / w) / 0.2f;
            rk = gtr[b*GG + sassign[src]];
        }
        ((float4*)(out + OFF_DELTAS + b*KK*4))[slot] = d;
        out[OFF_RANKS + b*KK + slot] = (float)rk;
    }

    // ── bulk outputs: 4 slots, one float4 per thread per slot (obj + spatial) ──
    const int row  = t >> 3;          // 0..31
    const int col0 = (t & 7) << 2;    // 0,4,...,28
    int r0 = 0, r1 = 0;
    bool inner = (row >= 4 && row < 28);
    if (inner) { int i = row - 4; r0 = 20*i + 9; r1 = r0 + 1; }

    #pragma unroll
    for (int j = 0; j < SPB; j++) {
        const int slot = slot0 + j;
        const int gidx = b*KK + slot;
        const int src  = sperm[slot];

        // obj gather
        const float4* in = (const float4*)(feat + (size_t)(b*KK + src) * 1024);
        ((float4*)(out + OFF_OBJ + (size_t)gidx * 1024))[t] = in[t];

        // spatial feature (closed-form resize_with_pad, ratio 20)
        const bool pos = (sposf[src] != 0);
        float4 rg = pos ? sgt[sassign[src]] : make_float4(0.f, 0.f, 0.f, 0.f);

        const float wy1 = 128.0f/1023.0f;
        const float wsy = (895.0f/1023.0f) - (128.0f/1023.0f);
        float by1 = (rg.x - wy1) / wsy;
        float by2 = (rg.z - wy1) / wsy;
        int py1 = (int)rintf(__fmul_rn(by1, 479.0f));
        int px1 = (int)rintf(__fmul_rn(rg.y, 639.0f));
        int py2 = (int)rintf(__fadd_rn(__fmul_rn(by2, 479.0f), 1.0f));
        int px2 = (int)rintf(__fadd_rn(__fmul_rn(rg.w, 639.0f), 1.0f));
        int area = (py2 - py1) * (px2 - px1);
        if (area <= 0) { py1 = px1 = py2 = px2 = 0; }

        float4 v = make_float4(0.f, 0.f, 0.f, 0.f);
        if (inner) {
            int ry = (int)((py1 < r0) && (r0 < py2)) + (int)((py1 < r1) && (r1 < py2));
            if (ry) {
                float fr = 0.25f * (float)ry;
                #pragma unroll
                for (int c = 0; c < 4; c++) {
                    int col = col0 + c;
                    int c0 = 20*col + 9, c1 = c0 + 1;
                    int cx = (int)((px1 < c0) && (c0 < px2)) + (int)((px1 < c1) && (c1 < px2));
                    ((float*)&v)[c] = fr * (float)cx;
                }
            }
        }
        ((float4*)(out + OFF_SPATIAL + (size_t)gidx * 1024))[t] = v;
    }
}

extern "C" void kernel_launch(void* const* d_in, const int* in_sizes, int n_in,
                              void* d_out, int out_size)
{
    const float* props = (const float*)d_in[0];   // [4,128,4]
    const float* feat  = (const float*)d_in[1];   // [4,128,1,1,1024]
    const float* gtb   = (const float*)d_in[2];   // [4,128,4]
    const int*   gtr   = (const int*)d_in[3];     // [4,128]
    float* out = (float*)d_out;

    fused_kernel<<<NBLK, 256>>>(props, feat, gtb, gtr, out);
}